// round 8
// baseline (speedup 1.0000x reference)
#include <cuda_runtime.h>
#include <cstdint>

// Problem constants
#define B_   4
#define T_   4096
#define DIM_ 1024
#define H_   16
#define KP_  256
#define DH_  64
#define F3_  (3 * DIM_)   // 3072

// ---------------------------------------------------------------------------
// Scratch (device globals — no runtime allocation allowed)
// ---------------------------------------------------------------------------
__device__ float g_qkv[(size_t)B_ * T_ * F3_];      // [B,T,3072]   192 MiB
__device__ float g_kp [(size_t)B_ * H_ * KP_ * DH_]; // [B,H,256,64]   4 MiB
__device__ float g_vp [(size_t)B_ * H_ * KP_ * DH_]; // [B,H,256,64]   4 MiB
__device__ float g_ao [(size_t)B_ * T_ * DIM_];      // [B,T,1024]    64 MiB

// ---------------------------------------------------------------------------
// Kernel 1/4: classic smem-tiled SGEMM  C[M,N] = A[M,K] * B[K,N]  (row-major)
// BM=BN=128, BK=16, 256 threads, 8x8 per thread.
// M,N,K all multiples of the tile sizes for this problem.
// ---------------------------------------------------------------------------
__global__ __launch_bounds__(256) void sgemm128(const float* __restrict__ A,
                                                const float* __restrict__ Bm,
                                                float* __restrict__ C,
                                                int M, int N, int K)
{
    const int BM = 128, BN = 128, BK = 16;
    __shared__ float As[BK][BM];   // stored transposed: As[k][m]
    __shared__ float Bs[BK][BN];

    const int tid  = threadIdx.x;
    const int brow = blockIdx.y;
    const int bcol = blockIdx.x;

    const float* Ab = A + (size_t)brow * BM * K;
    const float* Bb = Bm + (size_t)bcol * BN;

    const int aRow = tid >> 2;          // 0..63 (with +64 second half)
    const int aCol = (tid & 3) * 4;     // 0,4,8,12
    const int bRow = tid >> 5;          // 0..7  (with +8 second half)
    const int bCol = (tid & 31) * 4;    // 0..124

    const int trow = (tid >> 4) * 8;    // 0..120
    const int tcol = (tid & 15) * 8;    // 0..120

    float acc[8][8];
#pragma unroll
    for (int i = 0; i < 8; i++)
#pragma unroll
        for (int j = 0; j < 8; j++) acc[i][j] = 0.f;

    for (int k0 = 0; k0 < K; k0 += BK) {
        // Load A tile (transpose into As)
#pragma unroll
        for (int i = 0; i < 2; i++) {
            int r = aRow + i * 64;
            float4 v = *(const float4*)(Ab + (size_t)r * K + k0 + aCol);
            As[aCol + 0][r] = v.x;
            As[aCol + 1][r] = v.y;
            As[aCol + 2][r] = v.z;
            As[aCol + 3][r] = v.w;
        }
        // Load B tile
#pragma unroll
        for (int i = 0; i < 2; i++) {
            int r = bRow + i * 8;
            *(float4*)&Bs[r][bCol] = *(const float4*)(Bb + (size_t)(k0 + r) * N + bCol);
        }
        __syncthreads();

#pragma unroll
        for (int kk = 0; kk < BK; kk++) {
            float ra[8], rb[8];
            *(float4*)&ra[0] = *(float4*)&As[kk][trow];
            *(float4*)&ra[4] = *(float4*)&As[kk][trow + 4];
            *(float4*)&rb[0] = *(float4*)&Bs[kk][tcol];
            *(float4*)&rb[4] = *(float4*)&Bs[kk][tcol + 4];
#pragma unroll
            for (int i = 0; i < 8; i++)
#pragma unroll
                for (int j = 0; j < 8; j++)
                    acc[i][j] += ra[i] * rb[j];
        }
        __syncthreads();
    }

#pragma unroll
    for (int i = 0; i < 8; i++) {
        float* cp = C + (size_t)(brow * BM + trow + i) * N + bcol * BN + tcol;
        float4 v0 = make_float4(acc[i][0], acc[i][1], acc[i][2], acc[i][3]);
        float4 v1 = make_float4(acc[i][4], acc[i][5], acc[i][6], acc[i][7]);
        *(float4*)cp       = v0;
        *(float4*)(cp + 4) = v1;
    }
}

// ---------------------------------------------------------------------------
// Kernel 2: Linformer projection.
//   kp[b,h,k,d] = sum_j proj[j,k] * qkv[b,j, 48*d + 16 + h]   (and vp with +32)
// grid = (B*H, 2), block = 256. Each block computes the full [256,64] tile.
// Thread: 4 kproj rows x 16 d-cols register tile (64 accumulators).
// ---------------------------------------------------------------------------
__global__ __launch_bounds__(256) void proj_kernel(const float* __restrict__ proj)
{
    __shared__ float kv_s[32][64];    //  8 KB
    __shared__ float pj_s[32][256];   // 32 KB

    const int bh  = blockIdx.x;            // b*16 + h
    const int b   = bh >> 4;
    const int h   = bh & 15;
    const int off = ((int)blockIdx.y + 1) * 16;   // 16 for k, 32 for v
    const int tid = threadIdx.x;
    const int rg  = tid >> 2;              // 0..63 -> rows rg*4 .. rg*4+3
    const int dg  = tid & 3;               // d base = dg*16

    float acc[4][16];
#pragma unroll
    for (int i = 0; i < 4; i++)
#pragma unroll
        for (int t = 0; t < 16; t++) acc[i][t] = 0.f;

    const float* qb = g_qkv + (size_t)b * T_ * F3_ + off + h;

    for (int j0 = 0; j0 < T_; j0 += 32) {
        // gather k/v tile: kv_s[jj][d] = qkv[b, j0+jj, 48d + off + h]
#pragma unroll
        for (int i = 0; i < 8; i++) {
            int e  = tid + i * 256;
            int jj = e >> 6;
            int d  = e & 63;
            kv_s[jj][d] = qb[(size_t)(j0 + jj) * F3_ + d * 48];
        }
        // proj tile (coalesced)
#pragma unroll
        for (int i = 0; i < 8; i++) {
            int e4 = tid + i * 256;
            int jj = e4 >> 6;
            int c4 = (e4 & 63) * 4;
            *(float4*)&pj_s[jj][c4] = *(const float4*)(proj + (size_t)(j0 + jj) * KP_ + c4);
        }
        __syncthreads();

#pragma unroll 2
        for (int jj = 0; jj < 32; jj++) {
            float4 pv = *(float4*)&pj_s[jj][rg * 4];
            float pa[4] = {pv.x, pv.y, pv.z, pv.w};
            float kvv[16];
            *(float4*)&kvv[0]  = *(float4*)&kv_s[jj][dg * 16 + 0];
            *(float4*)&kvv[4]  = *(float4*)&kv_s[jj][dg * 16 + 4];
            *(float4*)&kvv[8]  = *(float4*)&kv_s[jj][dg * 16 + 8];
            *(float4*)&kvv[12] = *(float4*)&kv_s[jj][dg * 16 + 12];
#pragma unroll
            for (int i = 0; i < 4; i++)
#pragma unroll
                for (int t = 0; t < 16; t++)
                    acc[i][t] += pa[i] * kvv[t];
        }
        __syncthreads();
    }

    float* outp = (blockIdx.y ? g_vp : g_kp)
                + ((size_t)bh * KP_ + rg * 4) * DH_ + dg * 16;
#pragma unroll
    for (int i = 0; i < 4; i++) {
        float* rp = outp + (size_t)i * DH_;
        *(float4*)(rp + 0)  = make_float4(acc[i][0],  acc[i][1],  acc[i][2],  acc[i][3]);
        *(float4*)(rp + 4)  = make_float4(acc[i][4],  acc[i][5],  acc[i][6],  acc[i][7]);
        *(float4*)(rp + 8)  = make_float4(acc[i][8],  acc[i][9],  acc[i][10], acc[i][11]);
        *(float4*)(rp + 12) = make_float4(acc[i][12], acc[i][13], acc[i][14], acc[i][15]);
    }
}

// ---------------------------------------------------------------------------
// Kernel 3: fused attention. One thread = one query row (online softmax is
// entirely thread-local). grid = B*H*(T/256) = 1024, block = 256.
// k/v projected tiles staged through smem in chunks of 32 rows.
// ---------------------------------------------------------------------------
__global__ __launch_bounds__(256) void attn_kernel()
{
    __shared__ float kp_s[32][64];   // 8 KB
    __shared__ float vp_s[32][64];   // 8 KB

    const int bx    = blockIdx.x;
    const int chunk = bx & 15;       // T/256 = 16 chunks
    const int bh    = bx >> 4;       // 0..63
    const int b     = bh >> 4;
    const int h     = bh & 15;
    const int tid   = threadIdx.x;
    const int t     = chunk * 256 + tid;

    // gather q row: q[d] = qkv[b, t, 48d + h]
    const float* qp = g_qkv + (size_t)(b * T_ + t) * F3_ + h;
    float q[64];
#pragma unroll
    for (int d = 0; d < 64; d++) q[d] = qp[d * 48];

    float out[64];
#pragma unroll
    for (int d = 0; d < 64; d++) out[d] = 0.f;

    float m = -1e30f, l = 0.f;
    const float scale = 0.125f;   // DH^-0.5

    const float* kpb = g_kp + (size_t)bh * KP_ * DH_;
    const float* vpb = g_vp + (size_t)bh * KP_ * DH_;

    for (int kt = 0; kt < KP_ / 32; kt++) {
        // cooperative tile load (coalesced)
#pragma unroll
        for (int i = 0; i < 2; i++) {
            int e4 = tid + i * 256;
            int kk = e4 >> 4;
            int c4 = (e4 & 15) * 4;
            *(float4*)&kp_s[kk][c4] = *(const float4*)(kpb + (size_t)(kt * 32 + kk) * DH_ + c4);
            *(float4*)&vp_s[kk][c4] = *(const float4*)(vpb + (size_t)(kt * 32 + kk) * DH_ + c4);
        }
        __syncthreads();

        // scores for this tile
        float s[32];
#pragma unroll 2
        for (int kk = 0; kk < 32; kk++) {
            float a = 0.f;
#pragma unroll
            for (int d = 0; d < 64; d++) a += q[d] * kp_s[kk][d];
            s[kk] = a * scale;
        }

        float tm = -1e30f;
#pragma unroll
        for (int kk = 0; kk < 32; kk++) tm = fmaxf(tm, s[kk]);
        float nm   = fmaxf(m, tm);
        float corr = __expf(m - nm);
        l *= corr;
#pragma unroll
        for (int d = 0; d < 64; d++) out[d] *= corr;

#pragma unroll 2
        for (int kk = 0; kk < 32; kk++) {
            float e = __expf(s[kk] - nm);
            l += e;
#pragma unroll
            for (int d = 0; d < 64; d++) out[d] += e * vp_s[kk][d];
        }
        m = nm;
        __syncthreads();
    }

    const float inv = 1.f / l;
    float* op = g_ao + (size_t)(b * T_ + t) * DIM_ + h * DH_;
#pragma unroll
    for (int d = 0; d < 64; d += 4) {
        *(float4*)(op + d) = make_float4(out[d] * inv, out[d + 1] * inv,
                                         out[d + 2] * inv, out[d + 3] * inv);
    }
}

// ---------------------------------------------------------------------------
// Launch
// inputs (metadata order): x [B,T,1024], proj_mat [4096,256],
//                          Wqkv [1024,3072], W0 [1024,1024]; output fp32 [B,T,1024]
// ---------------------------------------------------------------------------
extern "C" void kernel_launch(void* const* d_in, const int* in_sizes, int n_in,
                              void* d_out, int out_size)
{
    const float* x    = (const float*)d_in[0];
    const float* proj = (const float*)d_in[1];
    const float* Wqkv = (const float*)d_in[2];
    const float* W0   = (const float*)d_in[3];
    float* out = (float*)d_out;

    void *qkv_p = nullptr, *ao_p = nullptr;
    cudaGetSymbolAddress(&qkv_p, g_qkv);
    cudaGetSymbolAddress(&ao_p,  g_ao);

    const int M = B_ * T_;   // 16384

    // 1) qkv = x @ Wqkv  -> g_qkv
    sgemm128<<<dim3(F3_ / 128, M / 128), 256>>>(x, Wqkv, (float*)qkv_p, M, F3_, DIM_);

    // 2) Linformer projection of k and v -> g_kp, g_vp
    proj_kernel<<<dim3(B_ * H_, 2), 256>>>(proj);

    // 3) fused attention -> g_ao
    attn_kernel<<<B_ * H_ * (T_ / 256), 256>>>();

    // 4) final projection: g_ao @ W0 -> d_out
    sgemm128<<<dim3(DIM_ / 128, M / 128), 256>>>((const float*)ao_p, W0, out, M, DIM_, DIM_);
}